// round 6
// baseline (speedup 1.0000x reference)
#include <cuda_runtime.h>
#include <cuda_bf16.h>

#define N_MAX 100000
#define E_MAX 3200000
#define NBLK_MAX 1024   // ceil(N_MAX/256) = 391 fits

// ---------------- scratch (device globals; no allocation allowed) ----------
__device__ int   g_degp[N_MAX];
__device__ int   g_degn[N_MAX];
__device__ float g_dinvp[N_MAX];
__device__ float g_dinvn[N_MAX];

__device__ int   g_bsump[NBLK_MAX];
__device__ int   g_bsumn[NBLK_MAX];
__device__ int   g_boffp[NBLK_MAX];
__device__ int   g_boffn[NBLK_MAX];
__device__ int   g_offp[N_MAX];
__device__ int   g_offn[N_MAX];
__device__ int   g_curp[N_MAX];
__device__ int   g_curn[N_MAX];

__device__ int2  g_packp[E_MAX];      // CSR-by-dst: {src, w as bits}
__device__ int2  g_packn[E_MAX];

__device__ float g_hp1[N_MAX * 16];   // x @ W1p
__device__ float g_hn1[N_MAX * 16];
__device__ float g_ap1[N_MAX * 16];   // relu(agg_p + b1p)
__device__ float g_an1[N_MAX * 16];   // relu(agg_n + b1n)

__device__ float g_hp2[N_MAX * 32];
__device__ float g_hn2[N_MAX * 32];

__device__ __forceinline__ float relu(float x) { return x > 0.f ? x : 0.f; }

// ---------------- degree / scan / CSR build ---------------------------------
__global__ void k_zero_deg(int n) {
    int i = blockIdx.x * blockDim.x + threadIdx.x;
    if (i < n) { g_degp[i] = 0; g_degn[i] = 0; }
}

__global__ void k_count_deg(const int* __restrict__ ep, const int* __restrict__ en, int E) {
    int i = blockIdx.x * blockDim.x + threadIdx.x;
    if (i < E) {
        atomicAdd(&g_degp[ep[E + i]], 1);
    } else if (i < 2 * E) {
        atomicAdd(&g_degn[en[E + (i - E)]], 1);
    }
}

__global__ void k_dinv(int n) {
    int i = blockIdx.x * blockDim.x + threadIdx.x;
    if (i < n) {
        g_dinvp[i] = rsqrtf((float)g_degp[i] + 1.0f);  // +1 self loop
        g_dinvn[i] = rsqrtf((float)g_degn[i] + 1.0f);
    }
}

// per-256-block degree sums
__global__ void k_scan1(int n) {
    __shared__ int s[256];
    int b = blockIdx.x, t = threadIdx.x, i = b * 256 + t;
    s[t] = (i < n) ? g_degp[i] : 0; __syncthreads();
    for (int d = 128; d > 0; d >>= 1) { if (t < d) s[t] += s[t + d]; __syncthreads(); }
    if (t == 0) g_bsump[b] = s[0];
    __syncthreads();
    s[t] = (i < n) ? g_degn[i] : 0; __syncthreads();
    for (int d = 128; d > 0; d >>= 1) { if (t < d) s[t] += s[t + d]; __syncthreads(); }
    if (t == 0) g_bsumn[b] = s[0];
}

// scan the block sums (one block of NBLK_MAX threads)
__global__ void k_scan2(int nb) {
    __shared__ int s[NBLK_MAX];
    int t = threadIdx.x;
    s[t] = (t < nb) ? g_bsump[t] : 0; __syncthreads();
    for (int d = 1; d < NBLK_MAX; d <<= 1) {
        int v = (t >= d) ? s[t - d] : 0; __syncthreads();
        s[t] += v; __syncthreads();
    }
    if (t < nb) g_boffp[t] = s[t] - g_bsump[t];
    __syncthreads();
    s[t] = (t < nb) ? g_bsumn[t] : 0; __syncthreads();
    for (int d = 1; d < NBLK_MAX; d <<= 1) {
        int v = (t >= d) ? s[t - d] : 0; __syncthreads();
        s[t] += v; __syncthreads();
    }
    if (t < nb) g_boffn[t] = s[t] - g_bsumn[t];
}

// per-node exclusive offsets + cursor init
__global__ void k_scan3(int n) {
    __shared__ int s[256];
    int b = blockIdx.x, t = threadIdx.x, i = b * 256 + t;
    int vp = (i < n) ? g_degp[i] : 0;
    s[t] = vp; __syncthreads();
    for (int d = 1; d < 256; d <<= 1) {
        int v = (t >= d) ? s[t - d] : 0; __syncthreads();
        s[t] += v; __syncthreads();
    }
    if (i < n) { int o = s[t] - vp + g_boffp[b]; g_offp[i] = o; g_curp[i] = o; }
    __syncthreads();
    int vn = (i < n) ? g_degn[i] : 0;
    s[t] = vn; __syncthreads();
    for (int d = 1; d < 256; d <<= 1) {
        int v = (t >= d) ? s[t - d] : 0; __syncthreads();
        s[t] += v; __syncthreads();
    }
    if (i < n) { int o = s[t] - vn + g_boffn[b]; g_offn[i] = o; g_curn[i] = o; }
}

// permute edges into CSR-by-dst slots; fuse norm computation here
__global__ void k_permute(const int* __restrict__ ep, const int* __restrict__ en, int E) {
    int i = blockIdx.x * blockDim.x + threadIdx.x;
    if (i < E) {
        int src = __ldg(&ep[i]), dst = __ldg(&ep[E + i]);
        float w = g_dinvp[src] * g_dinvp[dst];
        int slot = atomicAdd(&g_curp[dst], 1);
        g_packp[slot] = make_int2(src, __float_as_int(w));
    } else if (i < 2 * E) {
        int e = i - E;
        int src = __ldg(&en[e]), dst = __ldg(&en[E + e]);
        float w = g_dinvn[src] * g_dinvn[dst];
        int slot = atomicAdd(&g_curn[dst], 1);
        g_packn[slot] = make_int2(src, __float_as_int(w));
    }
}

// ---------------- GEMM 1 -----------------------------------------------------
// h = x[100k,128] @ [W1p | W1n]. Warp processes 4 nodes; lane = output feature
// (0-15 pos, 16-31 neg). W transposed in smem, reused across 4 nodes.
__global__ void k_gemm1(const float* __restrict__ x,
                        const float* __restrict__ W1p, const float* __restrict__ W1n,
                        int n) {
    __shared__ float sWt[32 * 132];
    int tid = threadIdx.x;
    for (int idx = tid; idx < 128 * 32; idx += 256) {
        int k = idx & 127, f = idx >> 7;
        sWt[f * 132 + k] = (f < 16) ? W1p[k * 16 + f] : W1n[k * 16 + (f - 16)];
    }
    __syncthreads();

    int lane = tid & 31;
    int nb = (blockIdx.x * 8 + (tid >> 5)) * 4;
    if (nb >= n) return;

    const float4* x0 = (const float4*)(x + (size_t)nb * 128);
    const float4* x1 = (nb + 1 < n) ? x0 + 32 : x0;
    const float4* x2 = (nb + 2 < n) ? x0 + 64 : x0;
    const float4* x3 = (nb + 3 < n) ? x0 + 96 : x0;

    float acc0 = 0.f, acc1 = 0.f, acc2 = 0.f, acc3 = 0.f;
#pragma unroll
    for (int k4 = 0; k4 < 32; k4++) {
        float4 w = *(const float4*)&sWt[lane * 132 + k4 * 4];
        float4 a = __ldg(&x0[k4]);
        float4 b = __ldg(&x1[k4]);
        float4 c = __ldg(&x2[k4]);
        float4 d = __ldg(&x3[k4]);
        acc0 += a.x * w.x + a.y * w.y + a.z * w.z + a.w * w.w;
        acc1 += b.x * w.x + b.y * w.y + b.z * w.z + b.w * w.w;
        acc2 += c.x * w.x + c.y * w.y + c.z * w.z + c.w * w.w;
        acc3 += d.x * w.x + d.y * w.y + d.z * w.z + d.w * w.w;
    }

    float accs[4] = {acc0, acc1, acc2, acc3};
    int f = lane & 15;
#pragma unroll
    for (int j = 0; j < 4; j++) {
        int node = nb + j;
        if (node >= n) break;
        if (lane < 16) g_hp1[node * 16 + f] = accs[j];
        else           g_hn1[node * 16 + f] = accs[j];
    }
}

// ---------------- layer-1 aggregation (CSR gather, no atomics) ---------------
// Warp per node: lanes 0-15 pos features, 16-31 neg features. Each half-warp
// reads one 64B h[src] row per edge, coalesced. Fuses self-loop + bias + relu.
__global__ void k_agg1(const float* __restrict__ b1p, const float* __restrict__ b1n,
                       int n) {
    int tid = threadIdx.x, lane = tid & 31;
    int node = blockIdx.x * 8 + (tid >> 5);
    if (node >= n) return;

    bool pos = lane < 16;
    int f = lane & 15;
    const int2*  pack = pos ? g_packp : g_packn;
    const float* h    = pos ? g_hp1   : g_hn1;
    const int*   off  = pos ? g_offp  : g_offn;
    const int*   deg  = pos ? g_degp  : g_degn;
    const float* dinv = pos ? g_dinvp : g_dinvn;

    int row = __ldg(&off[node]);
    int end = row + __ldg(&deg[node]);

    float acc = 0.f;
    int e = row;
    for (; e + 1 < end; e += 2) {
        int2 p0 = __ldg(&pack[e]);
        int2 p1 = __ldg(&pack[e + 1]);
        float v0 = __ldg(&h[(size_t)p0.x * 16 + f]);
        float v1 = __ldg(&h[(size_t)p1.x * 16 + f]);
        acc += v0 * __int_as_float(p0.y) + v1 * __int_as_float(p1.y);
    }
    if (e < end) {
        int2 p0 = __ldg(&pack[e]);
        acc += __ldg(&h[(size_t)p0.x * 16 + f]) * __int_as_float(p0.y);
    }

    float d = __ldg(&dinv[node]);
    acc += __ldg(&h[(size_t)node * 16 + f]) * d * d;   // self loop
    float b = pos ? __ldg(&b1p[f]) : __ldg(&b1n[f]);
    float r = relu(acc + b);
    if (pos) g_ap1[(size_t)node * 16 + f] = r;
    else     g_an1[(size_t)node * 16 + f] = r;
}

// ---------------- GEMM 2 -----------------------------------------------------
// h1 = ap1 - an1 (relu+bias already applied), then h1 @ [W2p | W2n].
__global__ void k_gemm2(const float* __restrict__ W2p, const float* __restrict__ W2n,
                        int n) {
    __shared__ float sW[16 * 64];
    int tid = threadIdx.x;
    for (int idx = tid; idx < 16 * 64; idx += 256) {
        int k = idx >> 6, l = idx & 63;
        sW[idx] = (l < 32) ? W2p[k * 32 + l] : W2n[k * 32 + (l - 32)];
    }
    __syncthreads();

    int t64 = tid & 63;
    int node = blockIdx.x * 4 + (tid >> 6);
    if (node >= n) return;

    const float* ap = g_ap1 + (size_t)node * 16;
    const float* an = g_an1 + (size_t)node * 16;
    float acc = 0.f;
#pragma unroll
    for (int k = 0; k < 16; k++) {
        float hv = __ldg(&ap[k]) - __ldg(&an[k]);
        acc += hv * sW[k * 64 + t64];
    }
    int f = t64 & 31;
    if (t64 < 32) g_hp2[node * 32 + f] = acc;
    else          g_hn2[node * 32 + f] = acc;
}

// ---------------- layer-2 aggregation + epilogue (fused) ---------------------
// Warp per node, lane = class. Pos and neg CSR gathers (128B coalesced rows),
// self loops, biases, relu-combine, then warp log_softmax.
__global__ void k_agg2(const float* __restrict__ b2p, const float* __restrict__ b2n,
                       float* __restrict__ out, int n) {
    int tid = threadIdx.x, lane = tid & 31;
    int node = blockIdx.x * 8 + (tid >> 5);
    if (node >= n) return;

    float accp = 0.f;
    {
        int row = __ldg(&g_offp[node]);
        int end = row + __ldg(&g_degp[node]);
        int e = row;
        for (; e + 1 < end; e += 2) {
            int2 p0 = __ldg(&g_packp[e]);
            int2 p1 = __ldg(&g_packp[e + 1]);
            float v0 = __ldg(&g_hp2[(size_t)p0.x * 32 + lane]);
            float v1 = __ldg(&g_hp2[(size_t)p1.x * 32 + lane]);
            accp += v0 * __int_as_float(p0.y) + v1 * __int_as_float(p1.y);
        }
        if (e < end) {
            int2 p0 = __ldg(&g_packp[e]);
            accp += __ldg(&g_hp2[(size_t)p0.x * 32 + lane]) * __int_as_float(p0.y);
        }
        float d = __ldg(&g_dinvp[node]);
        accp += __ldg(&g_hp2[(size_t)node * 32 + lane]) * d * d;
    }

    float accn = 0.f;
    {
        int row = __ldg(&g_offn[node]);
        int end = row + __ldg(&g_degn[node]);
        int e = row;
        for (; e + 1 < end; e += 2) {
            int2 p0 = __ldg(&g_packn[e]);
            int2 p1 = __ldg(&g_packn[e + 1]);
            float v0 = __ldg(&g_hn2[(size_t)p0.x * 32 + lane]);
            float v1 = __ldg(&g_hn2[(size_t)p1.x * 32 + lane]);
            accn += v0 * __int_as_float(p0.y) + v1 * __int_as_float(p1.y);
        }
        if (e < end) {
            int2 p0 = __ldg(&g_packn[e]);
            accn += __ldg(&g_hn2[(size_t)p0.x * 32 + lane]) * __int_as_float(p0.y);
        }
        float d = __ldg(&g_dinvn[node]);
        accn += __ldg(&g_hn2[(size_t)node * 32 + lane]) * d * d;
    }

    float z = relu(accp + __ldg(&b2p[lane])) - relu(accn + __ldg(&b2n[lane]));

    float m = z;
#pragma unroll
    for (int o = 16; o > 0; o >>= 1) m = fmaxf(m, __shfl_xor_sync(0xFFFFFFFF, m, o));
    float ex = expf(z - m);
    float s = ex;
#pragma unroll
    for (int o = 16; o > 0; o >>= 1) s += __shfl_xor_sync(0xFFFFFFFF, s, o);

    out[(size_t)node * 32 + lane] = z - m - logf(s);
}

// ---------------- launch ----------------------------------------------------
extern "C" void kernel_launch(void* const* d_in, const int* in_sizes, int n_in,
                              void* d_out, int out_size) {
    const float* x   = (const float*)d_in[0];
    const int*   ep  = (const int*)  d_in[1];
    const int*   en  = (const int*)  d_in[2];
    const float* W1p = (const float*)d_in[3];
    const float* b1p = (const float*)d_in[4];
    const float* W1n = (const float*)d_in[5];
    const float* b1n = (const float*)d_in[6];
    const float* W2p = (const float*)d_in[7];
    const float* b2p = (const float*)d_in[8];
    const float* W2n = (const float*)d_in[9];
    const float* b2n = (const float*)d_in[10];
    float* out = (float*)d_out;

    int n = in_sizes[0] / 128;     // 100000
    int E = in_sizes[1] / 2;       // 3200000

    int nb_n  = (n + 255) / 256;   // 391
    int nb_2e = (2 * E + 255) / 256;

    k_zero_deg <<<nb_n, 256>>>(n);
    k_count_deg<<<nb_2e, 256>>>(ep, en, E);
    k_dinv     <<<nb_n, 256>>>(n);
    k_scan1    <<<nb_n, 256>>>(n);
    k_scan2    <<<1, NBLK_MAX>>>(nb_n);
    k_scan3    <<<nb_n, 256>>>(n);
    k_permute  <<<nb_2e, 256>>>(ep, en, E);
    k_gemm1    <<<(n + 31) / 32, 256>>>(x, W1p, W1n, n);
    k_agg1     <<<(n + 7) / 8, 256>>>(b1p, b1n, n);
    k_gemm2    <<<(n + 3) / 4, 256>>>(W2p, W2n, n);
    k_agg2     <<<(n + 7) / 8, 256>>>(b2p, b2n, out, n);
}

// round 8
// speedup vs baseline: 1.0124x; 1.0124x over previous
#include <cuda_runtime.h>
#include <cuda_bf16.h>
#include <cuda_fp16.h>

#define N_MAX 100000
#define E_MAX 3200000
#define NBLK_MAX 1024   // ceil(N_MAX/256) = 391 fits

// ---------------- scratch (device globals; no allocation allowed) ----------
__device__ int   g_degp[N_MAX];
__device__ int   g_degn[N_MAX];
__device__ float g_dinvp[N_MAX];
__device__ float g_dinvn[N_MAX];

__device__ int   g_bsump[NBLK_MAX];
__device__ int   g_bsumn[NBLK_MAX];
__device__ int   g_boffp[NBLK_MAX];
__device__ int   g_boffn[NBLK_MAX];
__device__ int   g_offp[N_MAX];
__device__ int   g_offn[N_MAX];
__device__ int   g_curp[N_MAX];
__device__ int   g_curn[N_MAX];

__device__ int2  g_packp[E_MAX];      // CSR-by-dst: {src, w as fp32 bits}
__device__ int2  g_packn[E_MAX];

__device__ float g_hp1[N_MAX * 16];   // x @ W1p  (fp32 - precision anchor)
__device__ float g_hn1[N_MAX * 16];

__device__ __half g_hp2[N_MAX * 32];  // layer-2 features, fp16 (halves gather bytes)
__device__ __half g_hn2[N_MAX * 32];

__device__ __forceinline__ float relu(float x) { return x > 0.f ? x : 0.f; }

// ---------------- degree / scan / CSR build ---------------------------------
__global__ void k_zero_deg(int n) {
    int i = blockIdx.x * blockDim.x + threadIdx.x;
    if (i < n) { g_degp[i] = 0; g_degn[i] = 0; }
}

__global__ void k_count_deg(const int* __restrict__ ep, const int* __restrict__ en, int E) {
    int i = blockIdx.x * blockDim.x + threadIdx.x;
    if (i < E) {
        atomicAdd(&g_degp[ep[E + i]], 1);
    } else if (i < 2 * E) {
        atomicAdd(&g_degn[en[E + (i - E)]], 1);
    }
}

// dinv + per-256-block degree sums (merged)
__global__ void k_dinv_scan1(int n) {
    __shared__ int s[256];
    int b = blockIdx.x, t = threadIdx.x, i = b * 256 + t;
    int dp = (i < n) ? g_degp[i] : 0;
    int dn = (i < n) ? g_degn[i] : 0;
    if (i < n) {
        g_dinvp[i] = rsqrtf((float)dp + 1.0f);  // +1 self loop
        g_dinvn[i] = rsqrtf((float)dn + 1.0f);
    }
    s[t] = dp; __syncthreads();
    for (int d = 128; d > 0; d >>= 1) { if (t < d) s[t] += s[t + d]; __syncthreads(); }
    if (t == 0) g_bsump[b] = s[0];
    __syncthreads();
    s[t] = dn; __syncthreads();
    for (int d = 128; d > 0; d >>= 1) { if (t < d) s[t] += s[t + d]; __syncthreads(); }
    if (t == 0) g_bsumn[b] = s[0];
}

// scan the block sums (one block of NBLK_MAX threads)
__global__ void k_scan2(int nb) {
    __shared__ int s[NBLK_MAX];
    int t = threadIdx.x;
    s[t] = (t < nb) ? g_bsump[t] : 0; __syncthreads();
    for (int d = 1; d < NBLK_MAX; d <<= 1) {
        int v = (t >= d) ? s[t - d] : 0; __syncthreads();
        s[t] += v; __syncthreads();
    }
    if (t < nb) g_boffp[t] = s[t] - g_bsump[t];
    __syncthreads();
    s[t] = (t < nb) ? g_bsumn[t] : 0; __syncthreads();
    for (int d = 1; d < NBLK_MAX; d <<= 1) {
        int v = (t >= d) ? s[t - d] : 0; __syncthreads();
        s[t] += v; __syncthreads();
    }
    if (t < nb) g_boffn[t] = s[t] - g_bsumn[t];
}

// per-node exclusive offsets + cursor init
__global__ void k_scan3(int n) {
    __shared__ int s[256];
    int b = blockIdx.x, t = threadIdx.x, i = b * 256 + t;
    int vp = (i < n) ? g_degp[i] : 0;
    s[t] = vp; __syncthreads();
    for (int d = 1; d < 256; d <<= 1) {
        int v = (t >= d) ? s[t - d] : 0; __syncthreads();
        s[t] += v; __syncthreads();
    }
    if (i < n) { int o = s[t] - vp + g_boffp[b]; g_offp[i] = o; g_curp[i] = o; }
    __syncthreads();
    int vn = (i < n) ? g_degn[i] : 0;
    s[t] = vn; __syncthreads();
    for (int d = 1; d < 256; d <<= 1) {
        int v = (t >= d) ? s[t - d] : 0; __syncthreads();
        s[t] += v; __syncthreads();
    }
    if (i < n) { int o = s[t] - vn + g_boffn[b]; g_offn[i] = o; g_curn[i] = o; }
}

// permute edges into CSR-by-dst slots; fuse norm computation here
__global__ void k_permute(const int* __restrict__ ep, const int* __restrict__ en, int E) {
    int i = blockIdx.x * blockDim.x + threadIdx.x;
    if (i < E) {
        int src = __ldg(&ep[i]), dst = __ldg(&ep[E + i]);
        float w = g_dinvp[src] * g_dinvp[dst];
        int slot = atomicAdd(&g_curp[dst], 1);
        g_packp[slot] = make_int2(src, __float_as_int(w));
    } else if (i < 2 * E) {
        int e = i - E;
        int src = __ldg(&en[e]), dst = __ldg(&en[E + e]);
        float w = g_dinvn[src] * g_dinvn[dst];
        int slot = atomicAdd(&g_curn[dst], 1);
        g_packn[slot] = make_int2(src, __float_as_int(w));
    }
}

// ---------------- GEMM 1 -----------------------------------------------------
__global__ void k_gemm1(const float* __restrict__ x,
                        const float* __restrict__ W1p, const float* __restrict__ W1n,
                        int n) {
    __shared__ float sWt[32 * 132];
    int tid = threadIdx.x;
    for (int idx = tid; idx < 128 * 32; idx += 256) {
        int k = idx & 127, f = idx >> 7;
        sWt[f * 132 + k] = (f < 16) ? W1p[k * 16 + f] : W1n[k * 16 + (f - 16)];
    }
    __syncthreads();

    int lane = tid & 31;
    int nb = (blockIdx.x * 8 + (tid >> 5)) * 4;
    if (nb >= n) return;

    const float4* x0 = (const float4*)(x + (size_t)nb * 128);
    const float4* x1 = (nb + 1 < n) ? x0 + 32 : x0;
    const float4* x2 = (nb + 2 < n) ? x0 + 64 : x0;
    const float4* x3 = (nb + 3 < n) ? x0 + 96 : x0;

    float acc0 = 0.f, acc1 = 0.f, acc2 = 0.f, acc3 = 0.f;
#pragma unroll
    for (int k4 = 0; k4 < 32; k4++) {
        float4 w = *(const float4*)&sWt[lane * 132 + k4 * 4];
        float4 a = __ldg(&x0[k4]);
        float4 b = __ldg(&x1[k4]);
        float4 c = __ldg(&x2[k4]);
        float4 d = __ldg(&x3[k4]);
        acc0 += a.x * w.x + a.y * w.y + a.z * w.z + a.w * w.w;
        acc1 += b.x * w.x + b.y * w.y + b.z * w.z + b.w * w.w;
        acc2 += c.x * w.x + c.y * w.y + c.z * w.z + c.w * w.w;
        acc3 += d.x * w.x + d.y * w.y + d.z * w.z + d.w * w.w;
    }

    float accs[4] = {acc0, acc1, acc2, acc3};
    int f = lane & 15;
#pragma unroll
    for (int j = 0; j < 4; j++) {
        int node = nb + j;
        if (node >= n) break;
        if (lane < 16) g_hp1[node * 16 + f] = accs[j];
        else           g_hn1[node * 16 + f] = accs[j];
    }
}

// -------- fused layer-1 aggregation + bias/relu + layer-2 GEMM ---------------
// Warp per node. Lanes 0-15: pos features (gather h1p rows), 16-31: neg.
// After aggregation, h1 lives across lanes; shfl-broadcast each k and do the
// 16x64 GEMM in registers. Writes fp16 h2 rows directly.
__global__ void k_agg1gemm2(const float* __restrict__ b1p, const float* __restrict__ b1n,
                            const float* __restrict__ W2p, const float* __restrict__ W2n,
                            int n) {
    __shared__ float sW[16 * 64];    // [k][ f<32: W2p ; f>=32: W2n ]
    int tid = threadIdx.x;
    for (int idx = tid; idx < 16 * 64; idx += 512) {
        int k = idx >> 6, l = idx & 63;
        sW[idx] = (l < 32) ? W2p[k * 32 + l] : W2n[k * 32 + (l - 32)];
    }
    __syncthreads();

    int lane = tid & 31;
    int node = blockIdx.x * 16 + (tid >> 5);
    if (node >= n) return;

    bool pos = lane < 16;
    int f = lane & 15;
    const int2*  pack = pos ? g_packp : g_packn;
    const float* h    = pos ? g_hp1   : g_hn1;
    const int*   off  = pos ? g_offp  : g_offn;
    const int*   deg  = pos ? g_degp  : g_degn;
    const float* dinv = pos ? g_dinvp : g_dinvn;

    int row = __ldg(&off[node]);
    int end = row + __ldg(&deg[node]);

    float acc = 0.f;
    int e = row;
    for (; e + 3 < end; e += 4) {
        int2 p0 = __ldg(&pack[e]);
        int2 p1 = __ldg(&pack[e + 1]);
        int2 p2 = __ldg(&pack[e + 2]);
        int2 p3 = __ldg(&pack[e + 3]);
        float v0 = __ldg(&h[(size_t)p0.x * 16 + f]);
        float v1 = __ldg(&h[(size_t)p1.x * 16 + f]);
        float v2 = __ldg(&h[(size_t)p2.x * 16 + f]);
        float v3 = __ldg(&h[(size_t)p3.x * 16 + f]);
        acc += v0 * __int_as_float(p0.y) + v1 * __int_as_float(p1.y)
             + v2 * __int_as_float(p2.y) + v3 * __int_as_float(p3.y);
    }
    for (; e < end; e++) {
        int2 p0 = __ldg(&pack[e]);
        acc += __ldg(&h[(size_t)p0.x * 16 + f]) * __int_as_float(p0.y);
    }

    float d = __ldg(&dinv[node]);
    acc += __ldg(&h[(size_t)node * 16 + f]) * d * d;   // self loop
    float b = pos ? __ldg(&b1p[f]) : __ldg(&b1n[f]);
    float r = relu(acc + b);    // lanes 0-15: relu'd pos feature; 16-31: neg

    // layer-2 GEMM in registers via shfl broadcast
    float accp = 0.f, accn = 0.f;
#pragma unroll
    for (int k = 0; k < 16; k++) {
        float hp = __shfl_sync(0xFFFFFFFF, r, k);
        float hn = __shfl_sync(0xFFFFFFFF, r, k + 16);
        float hv = hp - hn;
        accp += hv * sW[k * 64 + lane];
        accn += hv * sW[k * 64 + 32 + lane];
    }
    g_hp2[(size_t)node * 32 + lane] = __float2half(accp);
    g_hn2[(size_t)node * 32 + lane] = __float2half(accn);
}

// ---------------- layer-2 aggregation + epilogue (fused) ---------------------
// Warp per node, lane = class. fp16 gathers (64B rows), self loops, biases,
// relu-combine, warp log_softmax.
__global__ void k_agg2(const float* __restrict__ b2p, const float* __restrict__ b2n,
                       float* __restrict__ out, int n) {
    int tid = threadIdx.x, lane = tid & 31;
    int node = blockIdx.x * 8 + (tid >> 5);
    if (node >= n) return;

    float accp = 0.f;
    {
        int row = __ldg(&g_offp[node]);
        int end = row + __ldg(&g_degp[node]);
        int e = row;
        for (; e + 3 < end; e += 4) {
            int2 p0 = __ldg(&g_packp[e]);
            int2 p1 = __ldg(&g_packp[e + 1]);
            int2 p2 = __ldg(&g_packp[e + 2]);
            int2 p3 = __ldg(&g_packp[e + 3]);
            float v0 = __half2float(__ldg(&g_hp2[(size_t)p0.x * 32 + lane]));
            float v1 = __half2float(__ldg(&g_hp2[(size_t)p1.x * 32 + lane]));
            float v2 = __half2float(__ldg(&g_hp2[(size_t)p2.x * 32 + lane]));
            float v3 = __half2float(__ldg(&g_hp2[(size_t)p3.x * 32 + lane]));
            accp += v0 * __int_as_float(p0.y) + v1 * __int_as_float(p1.y)
                  + v2 * __int_as_float(p2.y) + v3 * __int_as_float(p3.y);
        }
        for (; e < end; e++) {
            int2 p0 = __ldg(&g_packp[e]);
            accp += __half2float(__ldg(&g_hp2[(size_t)p0.x * 32 + lane])) * __int_as_float(p0.y);
        }
        float d = __ldg(&g_dinvp[node]);
        accp += __half2float(__ldg(&g_hp2[(size_t)node * 32 + lane])) * d * d;
    }

    float accn = 0.f;
    {
        int row = __ldg(&g_offn[node]);
        int end = row + __ldg(&g_degn[node]);
        int e = row;
        for (; e + 3 < end; e += 4) {
            int2 p0 = __ldg(&g_packn[e]);
            int2 p1 = __ldg(&g_packn[e + 1]);
            int2 p2 = __ldg(&g_packn[e + 2]);
            int2 p3 = __ldg(&g_packn[e + 3]);
            float v0 = __half2float(__ldg(&g_hn2[(size_t)p0.x * 32 + lane]));
            float v1 = __half2float(__ldg(&g_hn2[(size_t)p1.x * 32 + lane]));
            float v2 = __half2float(__ldg(&g_hn2[(size_t)p2.x * 32 + lane]));
            float v3 = __half2float(__ldg(&g_hn2[(size_t)p3.x * 32 + lane]));
            accn += v0 * __int_as_float(p0.y) + v1 * __int_as_float(p1.y)
                  + v2 * __int_as_float(p2.y) + v3 * __int_as_float(p3.y);
        }
        for (; e < end; e++) {
            int2 p0 = __ldg(&g_packn[e]);
            accn += __half2float(__ldg(&g_hn2[(size_t)p0.x * 32 + lane])) * __int_as_float(p0.y);
        }
        float d = __ldg(&g_dinvn[node]);
        accn += __half2float(__ldg(&g_hn2[(size_t)node * 32 + lane])) * d * d;
    }

    float z = relu(accp + __ldg(&b2p[lane])) - relu(accn + __ldg(&b2n[lane]));

    float m = z;
#pragma unroll
    for (int o = 16; o > 0; o >>= 1) m = fmaxf(m, __shfl_xor_sync(0xFFFFFFFF, m, o));
    float ex = expf(z - m);
    float s = ex;
#pragma unroll
    for (int o = 16; o > 0; o >>= 1) s += __shfl_xor_sync(0xFFFFFFFF, s, o);

    out[(size_t)node * 32 + lane] = z - m - logf(s);
}

// ---------------- launch ----------------------------------------------------
extern "C" void kernel_launch(void* const* d_in, const int* in_sizes, int n_in,
                              void* d_out, int out_size) {
    const float* x   = (const float*)d_in[0];
    const int*   ep  = (const int*)  d_in[1];
    const int*   en  = (const int*)  d_in[2];
    const float* W1p = (const float*)d_in[3];
    const float* b1p = (const float*)d_in[4];
    const float* W1n = (const float*)d_in[5];
    const float* b1n = (const float*)d_in[6];
    const float* W2p = (const float*)d_in[7];
    const float* b2p = (const float*)d_in[8];
    const float* W2n = (const float*)d_in[9];
    const float* b2n = (const float*)d_in[10];
    float* out = (float*)d_out;

    int n = in_sizes[0] / 128;     // 100000
    int E = in_sizes[1] / 2;       // 3200000

    int nb_n  = (n + 255) / 256;   // 391
    int nb_2e = (2 * E + 255) / 256;

    k_zero_deg  <<<nb_n, 256>>>(n);
    k_count_deg <<<nb_2e, 256>>>(ep, en, E);
    k_dinv_scan1<<<nb_n, 256>>>(n);
    k_scan2     <<<1, NBLK_MAX>>>(nb_n);
    k_scan3     <<<nb_n, 256>>>(n);
    k_permute   <<<nb_2e, 256>>>(ep, en, E);
    k_gemm1     <<<(n + 31) / 32, 256>>>(x, W1p, W1n, n);
    k_agg1gemm2 <<<(n + 15) / 16, 512>>>(b1p, b1n, W2p, W2n, n);
    k_agg2      <<<(n + 7) / 8, 256>>>(b2p, b2n, out, n);
}